// round 13
// baseline (speedup 1.0000x reference)
#include <cuda_runtime.h>
#include <cuda_fp16.h>
#include <cstdint>
#include <cstddef>

// Problem dims (fixed by the dataset)
#define SEQ_L 2048
#define BATCH 8
#define DIM   2048
#define M_ROWS (SEQ_L * BATCH)   // 16384
#define K_DIM  DIM
#define N_DIM  DIM
#define LANES  (BATCH * DIM)     // 16384

// Scan segmentation
#define NSEG 8
#define SEGLEN (SEQ_L / NSEG)    // 256

// GEMM tiling: CTA 64(M) x 128(N), 256 threads, 8 warps of 32x32, KT=64.
// 128B swizzled rows; 3-stage ring, one __syncthreads per chunk.
// ~75 regs/thread + 72KB smem -> 3 CTAs/SM = 24 warps/SM (6/SMSP).
#define MT 64
#define NT 128
#define KT 64
#define NCHUNK (K_DIM / KT)      // 32
#define ROWB 128
#define NSTAGE 3

#define OFF_A 0
#define OFF_B (64 * ROWB)            // 8192
#define STAGE ((64 + 128) * ROWB)    // 24576
#define SMEM_TOTAL (NSTAGE * STAGE)  // 73728 per CTA -> 3 CTAs/SM (216KB)

// Scratch (device globals — allocation-free rule)
__device__ __half g_ah[(size_t)M_ROWS * K_DIM];
__device__ __half g_wh[(size_t)N_DIM * K_DIM];
__device__ float  g_segend[NSEG * LANES];

// ---------------- PTX helpers (sm_80-era only: safe at compute_103) ----------------
__device__ __forceinline__ uint32_t smem_u32(const void* p) {
    uint32_t a;
    asm("{ .reg .u64 t; cvta.to.shared.u64 t, %1; cvt.u32.u64 %0, t; }"
        : "=r"(a) : "l"(p));
    return a;
}

__device__ __forceinline__ void cp_async16(uint32_t saddr, const void* gaddr) {
    asm volatile("cp.async.cg.shared.global [%0], [%1], 16;"
                 :: "r"(saddr), "l"(gaddr) : "memory");
}

__device__ __forceinline__ void ldsm_x4(uint32_t (&r)[4], uint32_t addr) {
    asm volatile("ldmatrix.sync.aligned.m8n8.x4.shared.b16 {%0,%1,%2,%3}, [%4];"
                 : "=r"(r[0]), "=r"(r[1]), "=r"(r[2]), "=r"(r[3]) : "r"(addr));
}

__device__ __forceinline__ void mma_f16(float (&d)[4], const uint32_t (&a)[4],
                                        const uint32_t* b) {
    asm volatile(
        "mma.sync.aligned.m16n8k16.row.col.f32.f16.f16.f32 "
        "{%0,%1,%2,%3}, {%4,%5,%6,%7}, {%8,%9}, {%0,%1,%2,%3};"
        : "+f"(d[0]), "+f"(d[1]), "+f"(d[2]), "+f"(d[3])
        : "r"(a[0]), "r"(a[1]), "r"(a[2]), "r"(a[3]), "r"(b[0]), "r"(b[1]));
}

// ---------------- Scan phase A (+ fused W->fp16): blocks x<64 scan, x>=64 convert ----
__global__ void __launch_bounds__(256) scanAW_kernel(const float* __restrict__ x,
                                                     const float* __restrict__ fparam,
                                                     const float* __restrict__ W) {
    if (blockIdx.x >= 64) {
        // W conversion: 512 blocks (64 x-slots x 8 y) x 256 threads x 8 float4
        const int wb = (blockIdx.x - 64) + blockIdx.y * 64;   // 0..511
        const float4* src = reinterpret_cast<const float4*>(W);
        const int base = wb * 2048 + threadIdx.x;
#pragma unroll
        for (int i = 0; i < 8; i++) {
            float4 v = src[base + i * 256];
            __half2* dst = reinterpret_cast<__half2*>(g_wh) + (size_t)(base + i * 256) * 2;
            dst[0] = __floats2half2_rn(v.x, v.y);
            dst[1] = __floats2half2_rn(v.z, v.w);
        }
        return;
    }
    const int lane = blockIdx.x * blockDim.x + threadIdx.x;  // 0..16383
    const int seg = blockIdx.y;
    const float f = 1.0f / (1.0f + expf(-fparam[lane & (DIM - 1)]));
    const float* px = x + (size_t)seg * SEGLEN * LANES + lane;
    float c = 0.0f;
    constexpr int U = 16;
    for (int t = 0; t < SEGLEN; t += U) {
        float xv[U];
#pragma unroll
        for (int u = 0; u < U; u++) xv[u] = px[(t + u) * LANES];
#pragma unroll
        for (int u = 0; u < U; u++) c = fmaf(f, c, xv[u]);
    }
    g_segend[seg * LANES + lane] = c;
}

// ---------------- Scan phase B: propagate carry, rescan, emit fp16 ----------
__global__ void __launch_bounds__(256) scanB_kernel(const float* __restrict__ x,
                                                    const float* __restrict__ xml,
                                                    const float* __restrict__ fparam) {
    const int lane = blockIdx.x * blockDim.x + threadIdx.x;
    const int seg = blockIdx.y;
    const float f = 1.0f / (1.0f + expf(-fparam[lane & (DIM - 1)]));
    const float omf = 1.0f - f;

    // f^SEGLEN by repeated squaring (SEGLEN = 256 = 2^8)
    float f256 = f;
#pragma unroll
    for (int i = 0; i < 8; i++) f256 *= f256;

    // G = global conv state entering this segment; fs = f^(seg*SEGLEN)
    float G = 0.0f, fs = 1.0f;
    for (int s = 0; s < seg; s++) {
        G = fmaf(f256, G, g_segend[s * LANES + lane]);
        fs *= f256;
    }

    float c = G;
    float m = xml[lane] * fs;
    const float* px = x + (size_t)seg * SEGLEN * LANES + lane;
    __half* ph = g_ah + (size_t)seg * SEGLEN * LANES + lane;

    constexpr int U = 16;
    for (int t = 0; t < SEGLEN; t += U) {
        float xv[U];
#pragma unroll
        for (int u = 0; u < U; u++) xv[u] = px[(t + u) * LANES];
#pragma unroll
        for (int u = 0; u < U; u++) {
            c = fmaf(f, c, xv[u]);
            m *= f;
            ph[(t + u) * LANES] = __float2half_rn(fmaf(omf, c, m));
        }
    }
}

// ---------------- GEMM: 1-pass fp16, fp32 accum, 32x32 warp tile, 3 CTAs/SM ----
// smem row r (128B) stores logical 16B-chunk c at physical chunk (c ^ (r&7)).
__device__ __forceinline__ void load_chunk(uint32_t sb, int tid, int m0, int n0,
                                           int ck, int stage) {
    const uint32_t tb = sb + (uint32_t)stage * STAGE;
    const int koff = ck * KT;
    // A: 64 rows x 128B = 512 x 16B; thread -> row=tid>>2, chunks (tid&3)*2, +1
    {
        const int row = tid >> 2;
        const int c0 = (tid & 3) * 2;
        const int sw = row & 7;
        const size_t ga = (size_t)(m0 + row) * K_DIM + koff + c0 * 8;
        const uint32_t sa = tb + OFF_A + (uint32_t)row * ROWB;
        cp_async16(sa + (uint32_t)((c0 ^ sw) << 4), g_ah + ga);
        cp_async16(sa + (uint32_t)(((c0 + 1) ^ sw) << 4), g_ah + ga + 8);
    }
    // B: 128 rows x 128B = 1024 x 16B; thread -> row=tid>>1, chunks (tid&1)*4..+3
    {
        const int row = tid >> 1;
        const int c0 = (tid & 1) * 4;
        const int sw = row & 7;
        const size_t gb = (size_t)(n0 + row) * K_DIM + koff + c0 * 8;
        const uint32_t sB = tb + OFF_B + (uint32_t)row * ROWB;
#pragma unroll
        for (int s = 0; s < 4; s++)
            cp_async16(sB + (uint32_t)(((c0 + s) ^ sw) << 4), g_wh + gb + s * 8);
    }
    asm volatile("cp.async.commit_group;" ::: "memory");
}

__global__ void __launch_bounds__(256, 3) gemm_kernel(float* __restrict__ out) {
    extern __shared__ char smem[];
    const uint32_t sb = smem_u32(smem);
    const int tid = threadIdx.x;
    const int lid = tid & 31;
    const int wid = tid >> 5;
    const int wm = wid & 1;      // 2 warps along M (32 rows each)
    const int wn = wid >> 1;     // 4 warps along N (32 cols each)
    const int n0 = blockIdx.x * NT;
    const int m0 = blockIdx.y * MT;

    float acc[2][4][4];
#pragma unroll
    for (int a = 0; a < 2; a++)
#pragma unroll
        for (int b = 0; b < 4; b++)
#pragma unroll
            for (int c = 0; c < 4; c++) acc[a][b][c] = 0.0f;

    // Per-lane ldmatrix row bases (swizzle XOR applied per k-step).
    uint32_t aRow[2], aSw[2], bRow[2], bSw[2];
    const uint32_t aC = (uint32_t)(lid >> 4);
    const uint32_t bC = (uint32_t)((lid >> 3) & 1);
#pragma unroll
    for (int mt = 0; mt < 2; mt++) {
        const uint32_t r = (uint32_t)(wm * 32 + mt * 16 + (lid & 15));
        aRow[mt] = r * ROWB;
        aSw[mt] = r & 7;
    }
#pragma unroll
    for (int p = 0; p < 2; p++) {
        const uint32_t r = (uint32_t)(wn * 32 + p * 16 + ((lid >> 4) << 3) + (lid & 7));
        bRow[p] = r * ROWB;
        bSw[p] = r & 7;
    }

    // Prologue: stages 0 and 1 in flight.
    load_chunk(sb, tid, m0, n0, 0, 0);
    load_chunk(sb, tid, m0, n0, 1, 1);

    int stage = 0;       // stage holding chunk i
    int wstage = 2;      // stage to write chunk i+2 into

    for (int i = 0; i < NCHUNK; i++) {
        if (i + 1 < NCHUNK) {
            asm volatile("cp.async.wait_group 1;" ::: "memory");
        } else {
            asm volatile("cp.async.wait_group 0;" ::: "memory");
        }
        // Single barrier: publishes chunk i AND retires reads of buffer wstage.
        __syncthreads();

        if (i + 2 < NCHUNK) {
            load_chunk(sb, tid, m0, n0, i + 2, wstage);
        }

        const uint32_t baseA = sb + (uint32_t)stage * STAGE + OFF_A;
        const uint32_t baseB = sb + (uint32_t)stage * STAGE + OFF_B;
#pragma unroll
        for (int ks = 0; ks < 4; ks++) {
            uint32_t afr[2][4], bfr[2][4];
#pragma unroll
            for (int mt = 0; mt < 2; mt++)
                ldsm_x4(afr[mt], baseA + aRow[mt]
                                 + (((aC + 2u * ks) ^ aSw[mt]) << 4));
#pragma unroll
            for (int p = 0; p < 2; p++)
                ldsm_x4(bfr[p], baseB + bRow[p]
                                + (((bC + 2u * ks) ^ bSw[p]) << 4));
#pragma unroll
            for (int mt = 0; mt < 2; mt++)
#pragma unroll
                for (int nt = 0; nt < 4; nt++)
                    mma_f16(acc[mt][nt], afr[mt], &bfr[nt >> 1][(nt & 1) * 2]);
        }

        stage = (stage + 1 == NSTAGE) ? 0 : stage + 1;
        wstage = (wstage + 1 == NSTAGE) ? 0 : wstage + 1;
    }

    // Epilogue: fragment lane l -> row l/4 (+8), cols 2(l%4), +1.
    const int l4 = lid >> 2;
    const int l2 = (lid & 3) * 2;
#pragma unroll
    for (int mt = 0; mt < 2; mt++) {
        const int r0 = m0 + wm * 32 + mt * 16 + l4;
#pragma unroll
        for (int nt = 0; nt < 4; nt++) {
            const int cn = n0 + wn * 32 + nt * 8 + l2;
            *reinterpret_cast<float2*>(out + (size_t)r0 * N_DIM + cn) =
                make_float2(acc[mt][nt][0], acc[mt][nt][1]);
            *reinterpret_cast<float2*>(out + (size_t)(r0 + 8) * N_DIM + cn) =
                make_float2(acc[mt][nt][2], acc[mt][nt][3]);
        }
    }
}

// ---------------- launch ----------------
extern "C" void kernel_launch(void* const* d_in, const int* in_sizes, int n_in,
                              void* d_out, int out_size) {
    const float *x = nullptr, *xml = nullptr, *fp = nullptr, *W = nullptr;
    for (int i = 0; i < n_in; i++) {
        int s = in_sizes[i];
        if (s == SEQ_L * BATCH * DIM)      x   = (const float*)d_in[i];
        else if (s == BATCH * DIM)         xml = (const float*)d_in[i];
        else if (s == DIM)                 fp  = (const float*)d_in[i];
        else if (s == DIM * DIM)           W   = (const float*)d_in[i];
    }

    cudaFuncSetAttribute(gemm_kernel, cudaFuncAttributeMaxDynamicSharedMemorySize, SMEM_TOTAL);

    scanAW_kernel<<<dim3(128, NSEG), 256>>>(x, fp, W);
    scanB_kernel<<<dim3(LANES / 256, NSEG), 256>>>(x, xml, fp);
    gemm_kernel<<<dim3(N_DIM / NT, M_ROWS / MT), 256, SMEM_TOTAL>>>((float*)d_out);
}

// round 14
// speedup vs baseline: 1.0698x; 1.0698x over previous
#include <cuda_runtime.h>
#include <cuda_fp16.h>
#include <cstdint>
#include <cstddef>

// Problem dims (fixed by the dataset)
#define SEQ_L 2048
#define BATCH 8
#define DIM   2048
#define M_ROWS (SEQ_L * BATCH)   // 16384
#define K_DIM  DIM
#define N_DIM  DIM
#define LANES  (BATCH * DIM)     // 16384

// Scan segmentation
#define NSEG 8
#define SEGLEN (SEQ_L / NSEG)    // 256

// GEMM tiling (R12 geometry — measured at the mma.sync issue ceiling):
// CTA 128(M) x 128(N), 256 threads, 8 warps of 64x32, KT=64,
// 128B swizzled rows, 3-stage ring, ONE __syncthreads per chunk.
#define MT 128
#define NT 128
#define KT 64
#define NCHUNK (K_DIM / KT)      // 32
#define ROWB 128
#define NSTAGE 3

#define OFF_A 0
#define OFF_B (128 * ROWB)           // 16384
#define STAGE ((128 + 128) * ROWB)   // 32768
#define SMEM_TOTAL (NSTAGE * STAGE)  // 98304 per CTA -> 2 CTAs/SM

// Scratch (device globals — allocation-free rule)
__device__ __half g_ah[(size_t)M_ROWS * K_DIM];
__device__ __half g_wh[(size_t)N_DIM * K_DIM];
__device__ float  g_segend[NSEG * LANES];

// ---------------- PTX helpers (sm_80-era only: safe at compute_103) ----------------
__device__ __forceinline__ uint32_t smem_u32(const void* p) {
    uint32_t a;
    asm("{ .reg .u64 t; cvta.to.shared.u64 t, %1; cvt.u32.u64 %0, t; }"
        : "=r"(a) : "l"(p));
    return a;
}

__device__ __forceinline__ void cp_async16(uint32_t saddr, const void* gaddr) {
    asm volatile("cp.async.cg.shared.global [%0], [%1], 16;"
                 :: "r"(saddr), "l"(gaddr) : "memory");
}

__device__ __forceinline__ void ldsm_x4(uint32_t (&r)[4], uint32_t addr) {
    asm volatile("ldmatrix.sync.aligned.m8n8.x4.shared.b16 {%0,%1,%2,%3}, [%4];"
                 : "=r"(r[0]), "=r"(r[1]), "=r"(r[2]), "=r"(r[3]) : "r"(addr));
}

__device__ __forceinline__ void mma_f16(float (&d)[4], const uint32_t (&a)[4],
                                        const uint32_t* b) {
    asm volatile(
        "mma.sync.aligned.m16n8k16.row.col.f32.f16.f16.f32 "
        "{%0,%1,%2,%3}, {%4,%5,%6,%7}, {%8,%9}, {%0,%1,%2,%3};"
        : "+f"(d[0]), "+f"(d[1]), "+f"(d[2]), "+f"(d[3])
        : "r"(a[0]), "r"(a[1]), "r"(a[2]), "r"(a[3]), "r"(b[0]), "r"(b[1]));
}

// ---------------- Scan phase A (+ fused W->fp16): blocks x<64 scan, x>=64 convert ----
__global__ void __launch_bounds__(256) scanAW_kernel(const float* __restrict__ x,
                                                     const float* __restrict__ fparam,
                                                     const float* __restrict__ W) {
    if (blockIdx.x >= 64) {
        // W conversion: 512 blocks (64 x-slots x 8 y) x 256 threads x 8 float4
        const int wb = (blockIdx.x - 64) + blockIdx.y * 64;   // 0..511
        const float4* src = reinterpret_cast<const float4*>(W);
        const int base = wb * 2048 + threadIdx.x;
#pragma unroll
        for (int i = 0; i < 8; i++) {
            float4 v = src[base + i * 256];
            __half2* dst = reinterpret_cast<__half2*>(g_wh) + (size_t)(base + i * 256) * 2;
            dst[0] = __floats2half2_rn(v.x, v.y);
            dst[1] = __floats2half2_rn(v.z, v.w);
        }
        return;
    }
    const int lane = blockIdx.x * blockDim.x + threadIdx.x;  // 0..16383
    const int seg = blockIdx.y;
    const float f = 1.0f / (1.0f + expf(-fparam[lane & (DIM - 1)]));
    const float* px = x + (size_t)seg * SEGLEN * LANES + lane;
    float c = 0.0f;
    constexpr int U = 16;
    for (int t = 0; t < SEGLEN; t += U) {
        float xv[U];
#pragma unroll
        for (int u = 0; u < U; u++) xv[u] = px[(t + u) * LANES];
#pragma unroll
        for (int u = 0; u < U; u++) c = fmaf(f, c, xv[u]);
    }
    g_segend[seg * LANES + lane] = c;
}

// ---------------- Scan phase B: propagate carry, rescan, emit fp16 ----------
__global__ void __launch_bounds__(256) scanB_kernel(const float* __restrict__ x,
                                                    const float* __restrict__ xml,
                                                    const float* __restrict__ fparam) {
    const int lane = blockIdx.x * blockDim.x + threadIdx.x;
    const int seg = blockIdx.y;
    const float f = 1.0f / (1.0f + expf(-fparam[lane & (DIM - 1)]));
    const float omf = 1.0f - f;

    // f^SEGLEN by repeated squaring (SEGLEN = 256 = 2^8)
    float f256 = f;
#pragma unroll
    for (int i = 0; i < 8; i++) f256 *= f256;

    // G = global conv state entering this segment; fs = f^(seg*SEGLEN)
    float G = 0.0f, fs = 1.0f;
    for (int s = 0; s < seg; s++) {
        G = fmaf(f256, G, g_segend[s * LANES + lane]);
        fs *= f256;
    }

    float c = G;
    float m = xml[lane] * fs;
    const float* px = x + (size_t)seg * SEGLEN * LANES + lane;
    __half* ph = g_ah + (size_t)seg * SEGLEN * LANES + lane;

    constexpr int U = 16;
    for (int t = 0; t < SEGLEN; t += U) {
        float xv[U];
#pragma unroll
        for (int u = 0; u < U; u++) xv[u] = px[(t + u) * LANES];
#pragma unroll
        for (int u = 0; u < U; u++) {
            c = fmaf(f, c, xv[u]);
            m *= f;
            ph[(t + u) * LANES] = __float2half_rn(fmaf(omf, c, m));
        }
    }
}

// ---------------- GEMM: 1-pass fp16, fp32 accum, KT=64 swizzled, single sync ----
// smem row r (128B) stores logical 16B-chunk c at physical chunk (c ^ (r&7)).
__device__ __forceinline__ void load_chunk(uint32_t sb, int tid, int m0, int n0,
                                           int ck, int stage) {
    const uint32_t tb = sb + (uint32_t)stage * STAGE;
    const int koff = ck * KT;
    const int row = tid >> 1;        // 0..127
    const int half = tid & 1;        // 64B half of the row
    const int sw = row & 7;
    // A: 128 rows x 128B
    {
        const size_t ga = (size_t)(m0 + row) * K_DIM + koff + half * 32;
        const uint32_t sa = tb + OFF_A + (uint32_t)row * ROWB;
#pragma unroll
        for (int s = 0; s < 4; s++) {
            const int c = half * 4 + s;
            cp_async16(sa + (uint32_t)((c ^ sw) << 4), g_ah + ga + s * 8);
        }
    }
    // B: 128 rows x 128B
    {
        const size_t gb = (size_t)(n0 + row) * K_DIM + koff + half * 32;
        const uint32_t sB = tb + OFF_B + (uint32_t)row * ROWB;
#pragma unroll
        for (int s = 0; s < 4; s++) {
            const int c = half * 4 + s;
            cp_async16(sB + (uint32_t)((c ^ sw) << 4), g_wh + gb + s * 8);
        }
    }
    asm volatile("cp.async.commit_group;" ::: "memory");
}

__global__ void __launch_bounds__(256, 2) gemm_kernel(float* __restrict__ out) {
    extern __shared__ char smem[];
    const uint32_t sb = smem_u32(smem);
    const int tid = threadIdx.x;
    const int lid = tid & 31;
    const int wid = tid >> 5;
    const int wm = wid & 1;      // 2 warps along M (64 rows each)
    const int wn = wid >> 1;     // 4 warps along N (32 cols each)
    const int n0 = blockIdx.x * NT;
    const int m0 = blockIdx.y * MT;

    float acc[4][4][4];
#pragma unroll
    for (int a = 0; a < 4; a++)
#pragma unroll
        for (int b = 0; b < 4; b++)
#pragma unroll
            for (int c = 0; c < 4; c++) acc[a][b][c] = 0.0f;

    // Per-lane ldmatrix row bases (swizzle XOR applied per k-step).
    uint32_t aRow[4], aSw[4], bRow[2], bSw[2];
    const uint32_t aC = (uint32_t)(lid >> 4);
    const uint32_t bC = (uint32_t)((lid >> 3) & 1);
#pragma unroll
    for (int mt = 0; mt < 4; mt++) {
        const uint32_t r = (uint32_t)(wm * 64 + mt * 16 + (lid & 15));
        aRow[mt] = r * ROWB;
        aSw[mt] = r & 7;
    }
#pragma unroll
    for (int p = 0; p < 2; p++) {
        const uint32_t r = (uint32_t)(wn * 32 + p * 16 + ((lid >> 4) << 3) + (lid & 7));
        bRow[p] = r * ROWB;
        bSw[p] = r & 7;
    }

    // Prologue: stages 0 and 1 in flight.
    load_chunk(sb, tid, m0, n0, 0, 0);
    load_chunk(sb, tid, m0, n0, 1, 1);

    int stage = 0;       // stage holding chunk i
    int wstage = 2;      // stage to write chunk i+2 into

    for (int i = 0; i < NCHUNK; i++) {
        if (i + 1 < NCHUNK) {
            asm volatile("cp.async.wait_group 1;" ::: "memory");
        } else {
            asm volatile("cp.async.wait_group 0;" ::: "memory");
        }
        // Single barrier: publishes chunk i AND retires reads of buffer wstage.
        __syncthreads();

        if (i + 2 < NCHUNK) {
            load_chunk(sb, tid, m0, n0, i + 2, wstage);
        }

        const uint32_t baseA = sb + (uint32_t)stage * STAGE + OFF_A;
        const uint32_t baseB = sb + (uint32_t)stage * STAGE + OFF_B;
#pragma unroll
        for (int ks = 0; ks < 4; ks++) {
            uint32_t afr[4][4], bfr[2][4];
#pragma unroll
            for (int mt = 0; mt < 4; mt++)
                ldsm_x4(afr[mt], baseA + aRow[mt]
                                 + (((aC + 2u * ks) ^ aSw[mt]) << 4));
#pragma unroll
            for (int p = 0; p < 2; p++)
                ldsm_x4(bfr[p], baseB + bRow[p]
                                + (((bC + 2u * ks) ^ bSw[p]) << 4));
#pragma unroll
            for (int mt = 0; mt < 4; mt++)
#pragma unroll
                for (int nt = 0; nt < 4; nt++)
                    mma_f16(acc[mt][nt], afr[mt], &bfr[nt >> 1][(nt & 1) * 2]);
        }

        stage = (stage + 1 == NSTAGE) ? 0 : stage + 1;
        wstage = (wstage + 1 == NSTAGE) ? 0 : wstage + 1;
    }

    // Epilogue: fragment lane l -> row l/4 (+8), cols 2(l%4), +1.
    const int l4 = lid >> 2;
    const int l2 = (lid & 3) * 2;
#pragma unroll
    for (int mt = 0; mt < 4; mt++) {
        const int r0 = m0 + wm * 64 + mt * 16 + l4;
#pragma unroll
        for (int nt = 0; nt < 4; nt++) {
            const int cn = n0 + wn * 32 + nt * 8 + l2;
            *reinterpret_cast<float2*>(out + (size_t)r0 * N_DIM + cn) =
                make_float2(acc[mt][nt][0], acc[mt][nt][1]);
            *reinterpret_cast<float2*>(out + (size_t)(r0 + 8) * N_DIM + cn) =
                make_float2(acc[mt][nt][2], acc[mt][nt][3]);
        }
    }
}

// ---------------- launch ----------------
extern "C" void kernel_launch(void* const* d_in, const int* in_sizes, int n_in,
                              void* d_out, int out_size) {
    const float *x = nullptr, *xml = nullptr, *fp = nullptr, *W = nullptr;
    for (int i = 0; i < n_in; i++) {
        int s = in_sizes[i];
        if (s == SEQ_L * BATCH * DIM)      x   = (const float*)d_in[i];
        else if (s == BATCH * DIM)         xml = (const float*)d_in[i];
        else if (s == DIM)                 fp  = (const float*)d_in[i];
        else if (s == DIM * DIM)           W   = (const float*)d_in[i];
    }

    cudaFuncSetAttribute(gemm_kernel, cudaFuncAttributeMaxDynamicSharedMemorySize, SMEM_TOTAL);

    scanAW_kernel<<<dim3(128, NSEG), 256>>>(x, fp, W);
    scanB_kernel<<<dim3(LANES / 256, NSEG), 256>>>(x, xml, fp);
    gemm_kernel<<<dim3(N_DIM / NT, M_ROWS / MT), 256, SMEM_TOTAL>>>((float*)d_out);
}

// round 15
// speedup vs baseline: 1.0706x; 1.0007x over previous
#include <cuda_runtime.h>
#include <cuda_fp16.h>
#include <cstdint>
#include <cstddef>

// Problem dims (fixed by the dataset)
#define SEQ_L 2048
#define BATCH 8
#define DIM   2048
#define M_ROWS (SEQ_L * BATCH)   // 16384
#define K_DIM  DIM
#define N_DIM  DIM
#define LANES  (BATCH * DIM)     // 16384

// Scan segmentation
#define NSEG 8
#define SEGLEN (SEQ_L / NSEG)    // 256

// GEMM tiling (R12 geometry — measured at the mma.sync issue ceiling):
// CTA 128(M) x 128(N), 256 threads, 8 warps of 64x32, KT=64,
// 128B swizzled rows, 3-stage ring, ONE __syncthreads per chunk.
#define MT 128
#define NT 128
#define KT 64
#define NCHUNK (K_DIM / KT)      // 32
#define ROWB 128
#define NSTAGE 3

#define OFF_A 0
#define OFF_B (128 * ROWB)           // 16384
#define STAGE ((128 + 128) * ROWB)   // 32768
#define SMEM_TOTAL (NSTAGE * STAGE)  // 98304 per CTA -> 2 CTAs/SM

// Scratch (device globals — allocation-free rule)
__device__ __half g_ah[(size_t)M_ROWS * K_DIM];
__device__ __half g_wh[(size_t)N_DIM * K_DIM];
__device__ float  g_segend[NSEG * LANES];

// ---------------- PTX helpers (sm_80-era only: safe at compute_103) ----------------
__device__ __forceinline__ uint32_t smem_u32(const void* p) {
    uint32_t a;
    asm("{ .reg .u64 t; cvta.to.shared.u64 t, %1; cvt.u32.u64 %0, t; }"
        : "=r"(a) : "l"(p));
    return a;
}

__device__ __forceinline__ void cp_async16(uint32_t saddr, const void* gaddr) {
    asm volatile("cp.async.cg.shared.global [%0], [%1], 16;"
                 :: "r"(saddr), "l"(gaddr) : "memory");
}

__device__ __forceinline__ void ldsm_x4(uint32_t (&r)[4], uint32_t addr) {
    asm volatile("ldmatrix.sync.aligned.m8n8.x4.shared.b16 {%0,%1,%2,%3}, [%4];"
                 : "=r"(r[0]), "=r"(r[1]), "=r"(r[2]), "=r"(r[3]) : "r"(addr));
}

__device__ __forceinline__ void mma_f16(float (&d)[4], const uint32_t (&a)[4],
                                        const uint32_t* b) {
    asm volatile(
        "mma.sync.aligned.m16n8k16.row.col.f32.f16.f16.f32 "
        "{%0,%1,%2,%3}, {%4,%5,%6,%7}, {%8,%9}, {%0,%1,%2,%3};"
        : "+f"(d[0]), "+f"(d[1]), "+f"(d[2]), "+f"(d[3])
        : "r"(a[0]), "r"(a[1]), "r"(a[2]), "r"(a[3]), "r"(b[0]), "r"(b[1]));
}

// ---------------- Scan phase A (+ fused W->fp16): blocks x<64 scan, x>=64 convert ----
__global__ void __launch_bounds__(256) scanAW_kernel(const float* __restrict__ x,
                                                     const float* __restrict__ fparam,
                                                     const float* __restrict__ W) {
    if (blockIdx.x >= 64) {
        // W conversion: 512 blocks (64 x-slots x 8 y) x 256 threads x 8 float4
        const int wb = (blockIdx.x - 64) + blockIdx.y * 64;   // 0..511
        const float4* src = reinterpret_cast<const float4*>(W);
        const int base = wb * 2048 + threadIdx.x;
#pragma unroll
        for (int i = 0; i < 8; i++) {
            float4 v = src[base + i * 256];
            __half2* dst = reinterpret_cast<__half2*>(g_wh) + (size_t)(base + i * 256) * 2;
            dst[0] = __floats2half2_rn(v.x, v.y);
            dst[1] = __floats2half2_rn(v.z, v.w);
        }
        return;
    }
    const int lane = blockIdx.x * blockDim.x + threadIdx.x;  // 0..16383
    const int seg = blockIdx.y;
    const float f = 1.0f / (1.0f + expf(-fparam[lane & (DIM - 1)]));
    const float* px = x + (size_t)seg * SEGLEN * LANES + lane;
    float c = 0.0f;
    constexpr int U = 16;
    for (int t = 0; t < SEGLEN; t += U) {
        float xv[U];
#pragma unroll
        for (int u = 0; u < U; u++) xv[u] = px[(t + u) * LANES];
#pragma unroll
        for (int u = 0; u < U; u++) c = fmaf(f, c, xv[u]);
    }
    g_segend[seg * LANES + lane] = c;
}

// ---------------- Scan phase B: propagate carry, rescan, emit fp16 ----------
__global__ void __launch_bounds__(256) scanB_kernel(const float* __restrict__ x,
                                                    const float* __restrict__ xml,
                                                    const float* __restrict__ fparam) {
    const int lane = blockIdx.x * blockDim.x + threadIdx.x;
    const int seg = blockIdx.y;
    const float f = 1.0f / (1.0f + expf(-fparam[lane & (DIM - 1)]));
    const float omf = 1.0f - f;

    // f^SEGLEN by repeated squaring (SEGLEN = 256 = 2^8)
    float f256 = f;
#pragma unroll
    for (int i = 0; i < 8; i++) f256 *= f256;

    // G = global conv state entering this segment; fs = f^(seg*SEGLEN)
    float G = 0.0f, fs = 1.0f;
    for (int s = 0; s < seg; s++) {
        G = fmaf(f256, G, g_segend[s * LANES + lane]);
        fs *= f256;
    }

    float c = G;
    float m = xml[lane] * fs;
    const float* px = x + (size_t)seg * SEGLEN * LANES + lane;
    __half* ph = g_ah + (size_t)seg * SEGLEN * LANES + lane;

    constexpr int U = 16;
    for (int t = 0; t < SEGLEN; t += U) {
        float xv[U];
#pragma unroll
        for (int u = 0; u < U; u++) xv[u] = px[(t + u) * LANES];
#pragma unroll
        for (int u = 0; u < U; u++) {
            c = fmaf(f, c, xv[u]);
            m *= f;
            ph[(t + u) * LANES] = __float2half_rn(fmaf(omf, c, m));
        }
    }
}

// ---------------- GEMM: 1-pass fp16, fp32 accum, KT=64 swizzled, single sync ----
// smem row r (128B) stores logical 16B-chunk c at physical chunk (c ^ (r&7)).
__device__ __forceinline__ void load_chunk(uint32_t sb, int tid, int m0, int n0,
                                           int ck, int stage) {
    const uint32_t tb = sb + (uint32_t)stage * STAGE;
    const int koff = ck * KT;
    const int row = tid >> 1;        // 0..127
    const int half = tid & 1;        // 64B half of the row
    const int sw = row & 7;
    // A: 128 rows x 128B
    {
        const size_t ga = (size_t)(m0 + row) * K_DIM + koff + half * 32;
        const uint32_t sa = tb + OFF_A + (uint32_t)row * ROWB;
#pragma unroll
        for (int s = 0; s < 4; s++) {
            const int c = half * 4 + s;
            cp_async16(sa + (uint32_t)((c ^ sw) << 4), g_ah + ga + s * 8);
        }
    }
    // B: 128 rows x 128B
    {
        const size_t gb = (size_t)(n0 + row) * K_DIM + koff + half * 32;
        const uint32_t sB = tb + OFF_B + (uint32_t)row * ROWB;
#pragma unroll
        for (int s = 0; s < 4; s++) {
            const int c = half * 4 + s;
            cp_async16(sB + (uint32_t)((c ^ sw) << 4), g_wh + gb + s * 8);
        }
    }
    asm volatile("cp.async.commit_group;" ::: "memory");
}

__global__ void __launch_bounds__(256, 2) gemm_kernel(float* __restrict__ out) {
    extern __shared__ char smem[];
    const uint32_t sb = smem_u32(smem);
    const int tid = threadIdx.x;
    const int lid = tid & 31;
    const int wid = tid >> 5;
    const int wm = wid & 1;      // 2 warps along M (64 rows each)
    const int wn = wid >> 1;     // 4 warps along N (32 cols each)
    const int n0 = blockIdx.x * NT;
    const int m0 = blockIdx.y * MT;

    float acc[4][4][4];
#pragma unroll
    for (int a = 0; a < 4; a++)
#pragma unroll
        for (int b = 0; b < 4; b++)
#pragma unroll
            for (int c = 0; c < 4; c++) acc[a][b][c] = 0.0f;

    // Per-lane ldmatrix row bases (swizzle XOR applied per k-step).
    uint32_t aRow[4], aSw[4], bRow[2], bSw[2];
    const uint32_t aC = (uint32_t)(lid >> 4);
    const uint32_t bC = (uint32_t)((lid >> 3) & 1);
#pragma unroll
    for (int mt = 0; mt < 4; mt++) {
        const uint32_t r = (uint32_t)(wm * 64 + mt * 16 + (lid & 15));
        aRow[mt] = r * ROWB;
        aSw[mt] = r & 7;
    }
#pragma unroll
    for (int p = 0; p < 2; p++) {
        const uint32_t r = (uint32_t)(wn * 32 + p * 16 + ((lid >> 4) << 3) + (lid & 7));
        bRow[p] = r * ROWB;
        bSw[p] = r & 7;
    }

    // Prologue: stages 0 and 1 in flight.
    load_chunk(sb, tid, m0, n0, 0, 0);
    load_chunk(sb, tid, m0, n0, 1, 1);

    int stage = 0;       // stage holding chunk i
    int wstage = 2;      // stage to write chunk i+2 into

    for (int i = 0; i < NCHUNK; i++) {
        if (i + 1 < NCHUNK) {
            asm volatile("cp.async.wait_group 1;" ::: "memory");
        } else {
            asm volatile("cp.async.wait_group 0;" ::: "memory");
        }
        // Single barrier: publishes chunk i AND retires reads of buffer wstage.
        __syncthreads();

        if (i + 2 < NCHUNK) {
            load_chunk(sb, tid, m0, n0, i + 2, wstage);
        }

        const uint32_t baseA = sb + (uint32_t)stage * STAGE + OFF_A;
        const uint32_t baseB = sb + (uint32_t)stage * STAGE + OFF_B;
#pragma unroll
        for (int ks = 0; ks < 4; ks++) {
            uint32_t afr[4][4], bfr[2][4];
#pragma unroll
            for (int mt = 0; mt < 4; mt++)
                ldsm_x4(afr[mt], baseA + aRow[mt]
                                 + (((aC + 2u * ks) ^ aSw[mt]) << 4));
#pragma unroll
            for (int p = 0; p < 2; p++)
                ldsm_x4(bfr[p], baseB + bRow[p]
                                + (((bC + 2u * ks) ^ bSw[p]) << 4));
#pragma unroll
            for (int mt = 0; mt < 4; mt++)
#pragma unroll
                for (int nt = 0; nt < 4; nt++)
                    mma_f16(acc[mt][nt], afr[mt], &bfr[nt >> 1][(nt & 1) * 2]);
        }

        stage = (stage + 1 == NSTAGE) ? 0 : stage + 1;
        wstage = (wstage + 1 == NSTAGE) ? 0 : wstage + 1;
    }

    // Epilogue: fragment lane l -> row l/4 (+8), cols 2(l%4), +1.
    const int l4 = lid >> 2;
    const int l2 = (lid & 3) * 2;
#pragma unroll
    for (int mt = 0; mt < 4; mt++) {
        const int r0 = m0 + wm * 64 + mt * 16 + l4;
#pragma unroll
        for (int nt = 0; nt < 4; nt++) {
            const int cn = n0 + wn * 32 + nt * 8 + l2;
            *reinterpret_cast<float2*>(out + (size_t)r0 * N_DIM + cn) =
                make_float2(acc[mt][nt][0], acc[mt][nt][1]);
            *reinterpret_cast<float2*>(out + (size_t)(r0 + 8) * N_DIM + cn) =
                make_float2(acc[mt][nt][2], acc[mt][nt][3]);
        }
    }
}

// ---------------- launch ----------------
extern "C" void kernel_launch(void* const* d_in, const int* in_sizes, int n_in,
                              void* d_out, int out_size) {
    const float *x = nullptr, *xml = nullptr, *fp = nullptr, *W = nullptr;
    for (int i = 0; i < n_in; i++) {
        int s = in_sizes[i];
        if (s == SEQ_L * BATCH * DIM)      x   = (const float*)d_in[i];
        else if (s == BATCH * DIM)         xml = (const float*)d_in[i];
        else if (s == DIM)                 fp  = (const float*)d_in[i];
        else if (s == DIM * DIM)           W   = (const float*)d_in[i];
    }

    cudaFuncSetAttribute(gemm_kernel, cudaFuncAttributeMaxDynamicSharedMemorySize, SMEM_TOTAL);

    scanAW_kernel<<<dim3(128, NSEG), 256>>>(x, fp, W);
    scanB_kernel<<<dim3(LANES / 256, NSEG), 256>>>(x, xml, fp);
    gemm_kernel<<<dim3(N_DIM / NT, M_ROWS / MT), 256, SMEM_TOTAL>>>((float*)d_out);
}

// round 16
// speedup vs baseline: 1.0727x; 1.0020x over previous
#include <cuda_runtime.h>
#include <cuda_fp16.h>
#include <cstdint>
#include <cstddef>

// Problem dims (fixed by the dataset)
#define SEQ_L 2048
#define BATCH 8
#define DIM   2048
#define M_ROWS (SEQ_L * BATCH)   // 16384
#define K_DIM  DIM
#define N_DIM  DIM
#define LANES  (BATCH * DIM)     // 16384

// Scan segmentation: fine for phase A (parallelism), coarser for phase B.
#define NSEG_A 64
#define SEGLEN_A (SEQ_L / NSEG_A)   // 32
#define NSEG_B 16
#define SEGLEN_B (SEQ_L / NSEG_B)   // 128
#define SUB_PER_B (NSEG_A / NSEG_B) // 4

// GEMM tiling (R12/R15 geometry — at the fp32-acc mma.sync ceiling):
// CTA 128(M) x 128(N), 256 threads, 8 warps of 64x32, KT=64,
// 128B swizzled rows, 3-stage ring, ONE __syncthreads per chunk.
#define MT 128
#define NT 128
#define KT 64
#define NCHUNK (K_DIM / KT)      // 32
#define ROWB 128
#define NSTAGE 3

#define OFF_A 0
#define OFF_B (128 * ROWB)           // 16384
#define STAGE ((128 + 128) * ROWB)   // 32768
#define SMEM_TOTAL (NSTAGE * STAGE)  // 98304 per CTA -> 2 CTAs/SM

// Scratch (device globals — allocation-free rule)
__device__ __half g_ah[(size_t)M_ROWS * K_DIM];
__device__ __half g_wh[(size_t)N_DIM * K_DIM];
__device__ float  g_segend[(size_t)NSEG_A * LANES];

// ---------------- PTX helpers (sm_80-era only: safe at compute_103) ----------------
__device__ __forceinline__ uint32_t smem_u32(const void* p) {
    uint32_t a;
    asm("{ .reg .u64 t; cvta.to.shared.u64 t, %1; cvt.u32.u64 %0, t; }"
        : "=r"(a) : "l"(p));
    return a;
}

__device__ __forceinline__ void cp_async16(uint32_t saddr, const void* gaddr) {
    asm volatile("cp.async.cg.shared.global [%0], [%1], 16;"
                 :: "r"(saddr), "l"(gaddr) : "memory");
}

__device__ __forceinline__ void ldsm_x4(uint32_t (&r)[4], uint32_t addr) {
    asm volatile("ldmatrix.sync.aligned.m8n8.x4.shared.b16 {%0,%1,%2,%3}, [%4];"
                 : "=r"(r[0]), "=r"(r[1]), "=r"(r[2]), "=r"(r[3]) : "r"(addr));
}

__device__ __forceinline__ void mma_f16(float (&d)[4], const uint32_t (&a)[4],
                                        const uint32_t* b) {
    asm volatile(
        "mma.sync.aligned.m16n8k16.row.col.f32.f16.f16.f32 "
        "{%0,%1,%2,%3}, {%4,%5,%6,%7}, {%8,%9}, {%0,%1,%2,%3};"
        : "+f"(d[0]), "+f"(d[1]), "+f"(d[2]), "+f"(d[3])
        : "r"(a[0]), "r"(a[1]), "r"(a[2]), "r"(a[3]), "r"(b[0]), "r"(b[1]));
}

// ---------------- Scan phase A (fine segments) + fused W->fp16 ----------------
// grid (64, NSEG_A + 8): y < NSEG_A -> scan sub-segment; y >= NSEG_A -> W convert.
__global__ void __launch_bounds__(256) scanAW_kernel(const float* __restrict__ x,
                                                     const float* __restrict__ fparam,
                                                     const float* __restrict__ W) {
    if (blockIdx.y >= NSEG_A) {
        // W conversion: 512 blocks (64 x-slots x 8 y) x 256 threads x 8 float4
        const int wb = blockIdx.x + (blockIdx.y - NSEG_A) * 64;   // 0..511
        const float4* src = reinterpret_cast<const float4*>(W);
        const int base = wb * 2048 + threadIdx.x;
#pragma unroll
        for (int i = 0; i < 8; i++) {
            float4 v = src[base + i * 256];
            __half2* dst = reinterpret_cast<__half2*>(g_wh) + (size_t)(base + i * 256) * 2;
            dst[0] = __floats2half2_rn(v.x, v.y);
            dst[1] = __floats2half2_rn(v.z, v.w);
        }
        return;
    }
    const int lane = blockIdx.x * blockDim.x + threadIdx.x;  // 0..16383
    const int seg = blockIdx.y;                              // 0..NSEG_A-1
    const float f = 1.0f / (1.0f + expf(-fparam[lane & (DIM - 1)]));
    const float* px = x + (size_t)seg * SEGLEN_A * LANES + lane;
    float c = 0.0f;
    constexpr int U = 16;
    for (int t = 0; t < SEGLEN_A; t += U) {
        float xv[U];
#pragma unroll
        for (int u = 0; u < U; u++) xv[u] = px[(t + u) * LANES];
#pragma unroll
        for (int u = 0; u < U; u++) c = fmaf(f, c, xv[u]);
    }
    g_segend[(size_t)seg * LANES + lane] = c;
}

// ---------------- Scan phase B: fold sub-carries, rescan, emit fp16 ----------
__global__ void __launch_bounds__(256) scanB_kernel(const float* __restrict__ x,
                                                    const float* __restrict__ xml,
                                                    const float* __restrict__ fparam) {
    const int lane = blockIdx.x * blockDim.x + threadIdx.x;
    const int seg = blockIdx.y;                              // 0..NSEG_B-1
    const float f = 1.0f / (1.0f + expf(-fparam[lane & (DIM - 1)]));
    const float omf = 1.0f - f;

    // f^SEGLEN_A (=32) by repeated squaring; f^SEGLEN_B (=128) from it.
    float fsub = f;
#pragma unroll
    for (int i = 0; i < 5; i++) fsub *= fsub;      // f^32
    float f128 = fsub * fsub;
    f128 *= f128;                                   // f^128

    // G = conv state entering this B-segment (fold sub-segment sums).
    float G = 0.0f;
    const int nsub = seg * SUB_PER_B;
    for (int a = 0; a < nsub; a++)
        G = fmaf(fsub, G, g_segend[(size_t)a * LANES + lane]);

    // fs = f^(seg*SEGLEN_B)
    float fs = 1.0f;
    for (int i = 0; i < seg; i++) fs *= f128;

    float c = G;
    float m = xml[lane] * fs;
    const float* px = x + (size_t)seg * SEGLEN_B * LANES + lane;
    __half* ph = g_ah + (size_t)seg * SEGLEN_B * LANES + lane;

    constexpr int U = 16;
    for (int t = 0; t < SEGLEN_B; t += U) {
        float xv[U];
#pragma unroll
        for (int u = 0; u < U; u++) xv[u] = px[(t + u) * LANES];
#pragma unroll
        for (int u = 0; u < U; u++) {
            c = fmaf(f, c, xv[u]);
            m *= f;
            ph[(t + u) * LANES] = __float2half_rn(fmaf(omf, c, m));
        }
    }
}

// ---------------- GEMM: 1-pass fp16, fp32 accum, KT=64 swizzled, single sync ----
// smem row r (128B) stores logical 16B-chunk c at physical chunk (c ^ (r&7)).
__device__ __forceinline__ void load_chunk(uint32_t sb, int tid, int m0, int n0,
                                           int ck, int stage) {
    const uint32_t tb = sb + (uint32_t)stage * STAGE;
    const int koff = ck * KT;
    const int row = tid >> 1;        // 0..127
    const int half = tid & 1;        // 64B half of the row
    const int sw = row & 7;
    // A: 128 rows x 128B
    {
        const size_t ga = (size_t)(m0 + row) * K_DIM + koff + half * 32;
        const uint32_t sa = tb + OFF_A + (uint32_t)row * ROWB;
#pragma unroll
        for (int s = 0; s < 4; s++) {
            const int c = half * 4 + s;
            cp_async16(sa + (uint32_t)((c ^ sw) << 4), g_ah + ga + s * 8);
        }
    }
    // B: 128 rows x 128B
    {
        const size_t gb = (size_t)(n0 + row) * K_DIM + koff + half * 32;
        const uint32_t sB = tb + OFF_B + (uint32_t)row * ROWB;
#pragma unroll
        for (int s = 0; s < 4; s++) {
            const int c = half * 4 + s;
            cp_async16(sB + (uint32_t)((c ^ sw) << 4), g_wh + gb + s * 8);
        }
    }
    asm volatile("cp.async.commit_group;" ::: "memory");
}

__global__ void __launch_bounds__(256, 2) gemm_kernel(float* __restrict__ out) {
    extern __shared__ char smem[];
    const uint32_t sb = smem_u32(smem);
    const int tid = threadIdx.x;
    const int lid = tid & 31;
    const int wid = tid >> 5;
    const int wm = wid & 1;      // 2 warps along M (64 rows each)
    const int wn = wid >> 1;     // 4 warps along N (32 cols each)
    const int n0 = blockIdx.x * NT;
    const int m0 = blockIdx.y * MT;

    float acc[4][4][4];
#pragma unroll
    for (int a = 0; a < 4; a++)
#pragma unroll
        for (int b = 0; b < 4; b++)
#pragma unroll
            for (int c = 0; c < 4; c++) acc[a][b][c] = 0.0f;

    // Per-lane ldmatrix row bases (swizzle XOR applied per k-step).
    uint32_t aRow[4], aSw[4], bRow[2], bSw[2];
    const uint32_t aC = (uint32_t)(lid >> 4);
    const uint32_t bC = (uint32_t)((lid >> 3) & 1);
#pragma unroll
    for (int mt = 0; mt < 4; mt++) {
        const uint32_t r = (uint32_t)(wm * 64 + mt * 16 + (lid & 15));
        aRow[mt] = r * ROWB;
        aSw[mt] = r & 7;
    }
#pragma unroll
    for (int p = 0; p < 2; p++) {
        const uint32_t r = (uint32_t)(wn * 32 + p * 16 + ((lid >> 4) << 3) + (lid & 7));
        bRow[p] = r * ROWB;
        bSw[p] = r & 7;
    }

    // Prologue: stages 0 and 1 in flight.
    load_chunk(sb, tid, m0, n0, 0, 0);
    load_chunk(sb, tid, m0, n0, 1, 1);

    int stage = 0;       // stage holding chunk i
    int wstage = 2;      // stage to write chunk i+2 into

    for (int i = 0; i < NCHUNK; i++) {
        if (i + 1 < NCHUNK) {
            asm volatile("cp.async.wait_group 1;" ::: "memory");
        } else {
            asm volatile("cp.async.wait_group 0;" ::: "memory");
        }
        // Single barrier: publishes chunk i AND retires reads of buffer wstage.
        __syncthreads();

        if (i + 2 < NCHUNK) {
            load_chunk(sb, tid, m0, n0, i + 2, wstage);
        }

        const uint32_t baseA = sb + (uint32_t)stage * STAGE + OFF_A;
        const uint32_t baseB = sb + (uint32_t)stage * STAGE + OFF_B;
#pragma unroll
        for (int ks = 0; ks < 4; ks++) {
            uint32_t afr[4][4], bfr[2][4];
#pragma unroll
            for (int mt = 0; mt < 4; mt++)
                ldsm_x4(afr[mt], baseA + aRow[mt]
                                 + (((aC + 2u * ks) ^ aSw[mt]) << 4));
#pragma unroll
            for (int p = 0; p < 2; p++)
                ldsm_x4(bfr[p], baseB + bRow[p]
                                + (((bC + 2u * ks) ^ bSw[p]) << 4));
#pragma unroll
            for (int mt = 0; mt < 4; mt++)
#pragma unroll
                for (int nt = 0; nt < 4; nt++)
                    mma_f16(acc[mt][nt], afr[mt], &bfr[nt >> 1][(nt & 1) * 2]);
        }

        stage = (stage + 1 == NSTAGE) ? 0 : stage + 1;
        wstage = (wstage + 1 == NSTAGE) ? 0 : wstage + 1;
    }

    // Epilogue: fragment lane l -> row l/4 (+8), cols 2(l%4), +1.
    const int l4 = lid >> 2;
    const int l2 = (lid & 3) * 2;
#pragma unroll
    for (int mt = 0; mt < 4; mt++) {
        const int r0 = m0 + wm * 64 + mt * 16 + l4;
#pragma unroll
        for (int nt = 0; nt < 4; nt++) {
            const int cn = n0 + wn * 32 + nt * 8 + l2;
            *reinterpret_cast<float2*>(out + (size_t)r0 * N_DIM + cn) =
                make_float2(acc[mt][nt][0], acc[mt][nt][1]);
            *reinterpret_cast<float2*>(out + (size_t)(r0 + 8) * N_DIM + cn) =
                make_float2(acc[mt][nt][2], acc[mt][nt][3]);
        }
    }
}

// ---------------- launch ----------------
extern "C" void kernel_launch(void* const* d_in, const int* in_sizes, int n_in,
                              void* d_out, int out_size) {
    const float *x = nullptr, *xml = nullptr, *fp = nullptr, *W = nullptr;
    for (int i = 0; i < n_in; i++) {
        int s = in_sizes[i];
        if (s == SEQ_L * BATCH * DIM)      x   = (const float*)d_in[i];
        else if (s == BATCH * DIM)         xml = (const float*)d_in[i];
        else if (s == DIM)                 fp  = (const float*)d_in[i];
        else if (s == DIM * DIM)           W   = (const float*)d_in[i];
    }

    cudaFuncSetAttribute(gemm_kernel, cudaFuncAttributeMaxDynamicSharedMemorySize, SMEM_TOTAL);

    scanAW_kernel<<<dim3(LANES / 256, NSEG_A + 8), 256>>>(x, fp, W);
    scanB_kernel<<<dim3(LANES / 256, NSEG_B), 256>>>(x, xml, fp);
    gemm_kernel<<<dim3(N_DIM / NT, M_ROWS / MT), 256, SMEM_TOTAL>>>((float*)d_out);
}